// round 16
// baseline (speedup 1.0000x reference)
#include <cuda_runtime.h>
#include <cuda_fp16.h>
#include <cstdint>

#define NT 1024
#define NH 2048
#define NI 2048
#define NEXP 16
#define NTOP 4
#define NSLOT (NT*NTOP)
#define ALPHA 1.702f
#define FLIMIT 7.0f
#define NCH 32               // K chunks of 64 halves

#define STRB 144             // bytes per smem row (128B data + 16B pad)
#define ABYTES (128*STRB)    // 18432
#define STAGEB (2*ABYTES)    // 36864 per stage (A+B)
#define NSTG 3
#define DSMEM_BYTES (NSTG*STAGEB)  // 110592

#define WELEM ((size_t)NEXP*NI*NH)   // elements per weight matrix
#define NSLICE 4
#define SLICE_I (NI/NSLICE)          // 512 I-rows per slice

// ---------------- scratch ----------------
__device__ int    g_tok_exp[NSLOT];
__device__ float  g_tok_w[NSLOT];
__device__ int    g_counts[NEXP];
__device__ int    g_offsets[NEXP];
__device__ int    g_token_list[NSLOT];
__device__ float  g_slot_w[NSLOT];
__device__ int    g_slot_of[NSLOT];
__device__ __half g_xh[(size_t)NT * NH];       // fp16 x
__device__ __half g_hbuf[(size_t)NSLOT * NI];  // fp16 h
__device__ __half g_gw16[WELEM];               // dequantized gate weights
__device__ __half g_uw16[WELEM];               // dequantized up weights
__device__ __half g_dw16[WELEM];               // dequantized down weights

// ---------------- helpers ----------------
__device__ __forceinline__ uint32_t f2h2(float a, float b){
    __half2 h = __floats2half2_rn(a, b);
    return *(uint32_t*)&h;
}
__device__ __forceinline__ uint32_t smem_u32(const void* p){
    uint32_t a;
    asm("{ .reg .u64 t; cvta.to.shared.u64 t, %1; cvt.u32.u64 %0, t; }" : "=r"(a) : "l"(p));
    return a;
}
__device__ __forceinline__ void cp16(uint32_t dst, const void* src){
    asm volatile("cp.async.cg.shared.global [%0], [%1], 16;" :: "r"(dst), "l"(src) : "memory");
}
__device__ __forceinline__ void cp_commit(){ asm volatile("cp.async.commit_group;" ::: "memory"); }
__device__ __forceinline__ void cp_wait1(){ asm volatile("cp.async.wait_group 1;" ::: "memory"); }

__device__ __forceinline__ void ldsm4(uint32_t& r0, uint32_t& r1, uint32_t& r2, uint32_t& r3, uint32_t addr){
    asm volatile("ldmatrix.sync.aligned.m8n8.x4.shared.b16 {%0,%1,%2,%3}, [%4];"
        : "=r"(r0), "=r"(r1), "=r"(r2), "=r"(r3) : "r"(addr));
}
__device__ __forceinline__ void mma_f16(float d[4], const uint32_t a[4], const uint32_t b[2]){
    asm volatile("mma.sync.aligned.m16n8k16.row.col.f32.f16.f16.f32 "
        "{%0,%1,%2,%3},{%4,%5,%6,%7},{%8,%9},{%0,%1,%2,%3};"
        : "+f"(d[0]),"+f"(d[1]),"+f"(d[2]),"+f"(d[3])
        : "r"(a[0]),"r"(a[1]),"r"(a[2]),"r"(a[3]),"r"(b[0]),"r"(b[1]));
}
__device__ __forceinline__ float act_fn(float g, float u){
    g = fminf(g, FLIMIT);
    u = fminf(fmaxf(u, -FLIMIT), FLIMIT);
    float sig = __fdividef(1.f, 1.f + __expf(-ALPHA*g));
    return (u + 1.f) * (g * sig);
}
__device__ __forceinline__ void red_add(float* addr, float v){
    asm volatile("red.global.add.f32 [%0], %1;" :: "l"(addr), "f"(v) : "memory");
}

// ---------------- K0a: dequant slice of gate+up (I-rows [c*512,(c+1)*512)) ----------------
// blockIdx.y: 0=gate, 1=up. One thread = 8 consecutive elements.
__global__ void __launch_bounds__(256)
dequant_gu_slice(const float* __restrict__ gblk, const float* __restrict__ gscl,
                 const float* __restrict__ ublk, const float* __restrict__ uscl,
                 int c)
{
    const float* blk; const float* scl; __half* out;
    if (blockIdx.y == 0){ blk = gblk; scl = gscl; out = g_gw16; }
    else                { blk = ublk; scl = uscl; out = g_uw16; }

    const size_t gid = (size_t)blockIdx.x * blockDim.x + threadIdx.x;
    const size_t g8  = gid * 8;
    const size_t per = (size_t)SLICE_I * NH;          // elems per expert slice
    const size_t e   = g8 / per;
    const size_t rem = g8 % per;
    const size_t elem = e*((size_t)NI*NH) + (size_t)c*per + rem;

    const float s = __ldg(&scl[elem >> 5]);
    float4 a = *(const float4*)(blk + elem);
    float4 b = *(const float4*)(blk + elem + 4);
    uint4 o;
    o.x = f2h2(a.x*s, a.y*s);
    o.y = f2h2(a.z*s, a.w*s);
    o.z = f2h2(b.x*s, b.y*s);
    o.w = f2h2(b.z*s, b.w*s);
    *(uint4*)(out + elem) = o;
}

// ---------------- K0b: dequant down (full) ----------------
__global__ void __launch_bounds__(256)
dequant_d(const float* __restrict__ dblk, const float* __restrict__ dscl)
{
    const size_t gid = (size_t)blockIdx.x * blockDim.x + threadIdx.x;
    const size_t base = gid * 8;
    const float s = __ldg(&dscl[gid >> 2]);
    float4 a = *(const float4*)(dblk + base);
    float4 b = *(const float4*)(dblk + base + 4);
    uint4 o;
    o.x = f2h2(a.x*s, a.y*s);
    o.y = f2h2(a.z*s, a.w*s);
    o.z = f2h2(b.x*s, b.y*s);
    o.w = f2h2(b.z*s, b.w*s);
    *(uint4*)(g_dw16 + base) = o;
}

// ---------------- K1: router (+ fp16 x emit + zero out row) ----------------
__global__ void router_kernel(const float* __restrict__ x,
                              const float* __restrict__ rw,
                              const float* __restrict__ rb,
                              float* __restrict__ out)
{
    __shared__ float sx[NH];
    __shared__ float slog[NEXP];
    const int t = blockIdx.x;
    for (int i = threadIdx.x; i < NH; i += blockDim.x)
        sx[i] = x[(size_t)t*NH + i];
    for (int i = threadIdx.x; i < NH/4; i += blockDim.x)
        ((float4*)(out + (size_t)t*NH))[i] = make_float4(0.f,0.f,0.f,0.f);
    __syncthreads();
    for (int i = threadIdx.x; i < NH/2; i += blockDim.x){
        *(uint32_t*)&g_xh[(size_t)t*NH + i*2] = f2h2(sx[i*2], sx[i*2+1]);
    }
    const int w = threadIdx.x >> 5;
    const int lane = threadIdx.x & 31;
    const float* wr = rw + (size_t)w*NH;
    float s = 0.f;
    for (int i = lane; i < NH; i += 32) s += sx[i]*wr[i];
    #pragma unroll
    for (int o=16;o>0;o>>=1) s += __shfl_xor_sync(0xffffffffu, s, o);
    if (lane==0) slog[w] = s + rb[w];
    __syncthreads();
    if (threadIdx.x==0){
        float v[NEXP];
        #pragma unroll
        for (int e=0;e<NEXP;e++) v[e]=slog[e];
        int idx[NTOP]; float val[NTOP];
        #pragma unroll
        for (int k=0;k<NTOP;k++){
            int bi=0; float bv=v[0];
            #pragma unroll
            for (int e=1;e<NEXP;e++){ if (v[e]>bv){bv=v[e];bi=e;} }
            idx[k]=bi; val[k]=bv; v[bi]=-3.4e38f;
        }
        float mx=val[0], ssum=0.f, ev[NTOP];
        #pragma unroll
        for(int k=0;k<NTOP;k++){ ev[k]=expf(val[k]-mx); ssum+=ev[k]; }
        float inv = 1.f/ssum;
        #pragma unroll
        for(int k=0;k<NTOP;k++){
            g_tok_exp[t*NTOP+k]=idx[k];
            g_tok_w[t*NTOP+k]=ev[k]*inv;
        }
    }
}

// ---------------- K2: build per-expert token lists (+ slot weights) ----------------
__global__ void build_lists_kernel()
{
    __shared__ int sc[NEXP], so[NEXP], scur[NEXP];
    const int t = threadIdx.x;
    if (t < NEXP) sc[t]=0;
    __syncthreads();
    int ex[NTOP];
    #pragma unroll
    for (int k=0;k<NTOP;k++){ ex[k]=g_tok_exp[t*NTOP+k]; atomicAdd(&sc[ex[k]],1); }
    __syncthreads();
    if (t==0){
        int acc=0;
        for(int e=0;e<NEXP;e++){ so[e]=acc; acc+=sc[e]; }
    }
    __syncthreads();
    if (t<NEXP){ g_counts[t]=sc[t]; g_offsets[t]=so[t]; scur[t]=so[t]; }
    __syncthreads();
    #pragma unroll
    for (int k=0;k<NTOP;k++){
        int slot = atomicAdd(&scur[ex[k]],1);
        g_token_list[slot]=t;
        g_slot_w[slot]=g_tok_w[t*NTOP+k];
        g_slot_of[t*NTOP+k]=slot;
    }
}

// ================= GEMM cores (fp16 A+B via cp.async): 256 thr, 8 warps =================

// ---------------- K3: gate+up GEMM slice + activation ----------------
// part selects I-slice: n0 = (blockIdx.x + part*8)*64
__global__ void __launch_bounds__(256,2)
gateup_full(const float* __restrict__ gbia, const float* __restrict__ ubia, int part)
{
    extern __shared__ float smf[];
    __shared__ int sTok[128];
    __shared__ float sGb[64], sUb[64];

    const int e   = blockIdx.y >> 3;
    const int mt  = blockIdx.y & 7;
    const int M   = g_counts[e];
    if (mt*128 >= M) return;
    const int Mrows = min(128, M - mt*128);
    const int off = g_offsets[e];
    const int n0  = (blockIdx.x + part*8) * 64;
    const int tid = threadIdx.x;
    const int wid = tid >> 5;
    const int lane = tid & 31;

    if (tid < 128){
        int ml = mt*128 + tid; if (ml > M-1) ml = M-1;
        sTok[tid] = g_token_list[off + ml];
    }
    if (tid < 64){
        sGb[tid] = gbia[(size_t)e*NI + n0 + tid];
        sUb[tid] = ubia[(size_t)e*NI + n0 + tid];
    }
    __syncthreads();

    const uint32_t smemBase = smem_u32(smf);
    const int r0s = tid >> 3;
    const int s  = tid & 7;

    const __half* srcA[4]; uint32_t offA[4];
    #pragma unroll
    for (int j=0;j<4;j++){
        int r = r0s + 32*j;
        srcA[j] = g_xh + (size_t)sTok[r]*NH + s*8;
        offA[j] = (uint32_t)(r*STRB + s*16);
    }
    const __half* srcB[4]; uint32_t offB[4];
    #pragma unroll
    for (int j=0;j<4;j++){
        int r = r0s + 32*j;
        const __half* w16 = (r < 64) ? g_gw16 : g_uw16;
        srcB[j] = w16 + ((size_t)e*NI + (size_t)(n0 + (r & 63)))*NH + s*8;
        offB[j] = (uint32_t)(ABYTES + r*STRB + s*16);
    }

    const int wm = (wid & 3) * 32;
    const int wn = (wid >> 2) * 32;
    const int fr = lane >> 2;
    const int fc = lane & 3;
    const bool active = (wm < Mrows);

    const uint32_t lmA0 = (uint32_t)((wm + (lane & 15))*STRB + (lane >> 4)*16);
    const uint32_t lmBg = (uint32_t)(ABYTES + (wn + ((lane>>4)&1)*8 + (lane&7))*STRB + ((lane>>3)&1)*16);

    float accg[2][4][4], accu[2][4][4];
    #pragma unroll
    for (int a=0;a<2;a++)
        #pragma unroll
        for (int b=0;b<4;b++)
            #pragma unroll
            for (int c=0;c<4;c++){ accg[a][b][c]=0.f; accu[a][b][c]=0.f; }

    #pragma unroll
    for (int st=0; st<2; st++){
        #pragma unroll
        for (int j=0;j<4;j++) cp16(smemBase + st*STAGEB + offA[j], srcA[j] + st*64);
        #pragma unroll
        for (int j=0;j<4;j++) cp16(smemBase + st*STAGEB + offB[j], srcB[j] + st*64);
        cp_commit();
    }
    cp_wait1();
    __syncthreads();

#define GU_MMA(ks) do { \
    uint32_t af[2][4]; \
    _Pragma("unroll") \
    for (int m2=0;m2<2;m2++) \
        ldsm4(af[m2][0],af[m2][1],af[m2][2],af[m2][3], stg + lmA0 + m2*2304 + (ks)*32); \
    uint32_t bg[4][2], bu[4][2]; \
    _Pragma("unroll") \
    for (int j=0;j<2;j++){ \
        ldsm4(bg[2*j][0],bg[2*j][1],bg[2*j+1][0],bg[2*j+1][1], stg + lmBg + j*2304 + (ks)*32); \
        ldsm4(bu[2*j][0],bu[2*j][1],bu[2*j+1][0],bu[2*j+1][1], stg + lmBg + 9216 + j*2304 + (ks)*32); \
    } \
    _Pragma("unroll") \
    for (int nt=0;nt<4;nt++) \
        _Pragma("unroll") \
        for (int m2=0;m2<2;m2++){ \
            mma_f16(accg[m2][nt], af[m2], bg[nt]); \
            mma_f16(accu[m2][nt], af[m2], bu[nt]); \
        } \
} while(0)

    for (int kc=0; kc<NCH; kc++){
        const uint32_t stg = smemBase + (kc%NSTG)*STAGEB;
        if (kc+2 < NCH){
            const uint32_t dst = smemBase + ((kc+2)%NSTG)*STAGEB;
            const int ka = (kc+2)*64;
            #pragma unroll
            for (int j=0;j<4;j++) cp16(dst + offA[j], srcA[j] + ka);
            #pragma unroll
            for (int j=0;j<4;j++) cp16(dst + offB[j], srcB[j] + ka);
        }
        cp_commit();
        if (active){ GU_MMA(0); GU_MMA(1); GU_MMA(2); GU_MMA(3); }
        cp_wait1();
        __syncthreads();
    }
#undef GU_MMA

    if (active){
        #pragma unroll
        for (int m2=0;m2<2;m2++){
            #pragma unroll
            for (int nt=0;nt<4;nt++){
                const int rl = wm + m2*16 + fr;
                const int cu = wn + nt*8 + fc*2;
                const float gb0 = sGb[cu], gb1 = sGb[cu+1];
                const float ub0 = sUb[cu], ub1 = sUb[cu+1];
                if (rl < Mrows){
                    float h0 = act_fn(accg[m2][nt][0]+gb0, accu[m2][nt][0]+ub0);
                    float h1 = act_fn(accg[m2][nt][1]+gb1, accu[m2][nt][1]+ub1);
                    *(uint32_t*)&g_hbuf[(size_t)(off + mt*128 + rl)*NI + n0 + cu] = f2h2(h0,h1);
                }
                if (rl+8 < Mrows){
                    float h0 = act_fn(accg[m2][nt][2]+gb0, accu[m2][nt][2]+ub0);
                    float h1 = act_fn(accg[m2][nt][3]+gb1, accu[m2][nt][3]+ub1);
                    *(uint32_t*)&g_hbuf[(size_t)(off + mt*128 + rl+8)*NI + n0 + cu] = f2h2(h0,h1);
                }
            }
        }
    }
}

// ---------------- K4: down GEMM + bias + fused weighted scatter ----------------
__global__ void __launch_bounds__(256,2)
down_kernel(const float* __restrict__ dbia, float* __restrict__ out)
{
    extern __shared__ float smf[];
    __shared__ float sDb[128];
    __shared__ int   sTk[128];
    __shared__ float sW[128];

    const int e   = blockIdx.y >> 3;
    const int mt  = blockIdx.y & 7;
    const int M   = g_counts[e];
    if (mt*128 >= M) return;
    const int Mrows = min(128, M - mt*128);
    const int off = g_offsets[e];
    const int n0  = blockIdx.x * 128;
    const int tid = threadIdx.x;
    const int wid = tid >> 5;
    const int lane = tid & 31;

    if (tid < 128){
        sDb[tid] = dbia[(size_t)e*NH + n0 + tid];
        int ml = mt*128 + tid; if (ml > M-1) ml = M-1;
        sTk[tid] = g_token_list[off + ml];
        sW[tid]  = g_slot_w[off + ml];
    }
    __syncthreads();

    const uint32_t smemBase = smem_u32(smf);
    const int r0s = tid >> 3;
    const int s  = tid & 7;

    const __half* srcA[4]; uint32_t offA[4];
    #pragma unroll
    for (int j=0;j<4;j++){
        int r = r0s + 32*j;
        int ml = mt*128 + r; if (ml > M-1) ml = M-1;
        srcA[j] = g_hbuf + (size_t)(off + ml)*NI + s*8;
        offA[j] = (uint32_t)(r*STRB + s*16);
    }
    const __half* srcB[4]; uint32_t offB[4];
    #pragma unroll
    for (int j=0;j<4;j++){
        int r = r0s + 32*j;
        srcB[j] = g_dw16 + ((size_t)e*NH + (size_t)(n0 + r))*NI + s*8;
        offB[j] = (uint32_t)(ABYTES + r*STRB + s*16);
    }

    const int wm = (wid & 3) * 32;
    const int wn = (wid >> 2) * 64;
    const int fr = lane >> 2;
    const int fc = lane & 3;
    const bool active = (wm < Mrows);

    const uint32_t lmA0 = (uint32_t)((wm + (lane & 15))*STRB + (lane >> 4)*16);
    const uint32_t lmB0 = (uint32_t)(ABYTES + (wn + ((lane>>4)&1)*8 + (lane&7))*STRB + ((lane>>3)&1)*16);

    float acc[2][8][4];
    #pragma unroll
    for (int a=0;a<2;a++)
        #pragma unroll
        for (int b=0;b<8;b++)
            #pragma unroll
            for (int c=0;c<4;c++) acc[a][b][c]=0.f;

    #pragma unroll
    for (int st=0; st<2; st++){
        #pragma unroll
        for (int j=0;j<4;j++) cp16(smemBase + st*STAGEB + offA[j], srcA[j] + st*64);
        #pragma unroll
        for (int j=0;j<4;j++) cp16(smemBase + st*STAGEB + offB[j], srcB[j] + st*64);
        cp_commit();
    }
    cp_wait1();
    __syncthreads();

#define DN_MMA(ks) do { \
    uint32_t af[2][4]; \
    _Pragma("unroll") \
    for (int m2=0;m2<2;m2++) \
        ldsm4(af[m2][0],af[m2][1],af[m2][2],af[m2][3], stg + lmA0 + m2*2304 + (ks)*32); \
    uint32_t bf[8][2]; \
    _Pragma("unroll") \
    for (int j=0;j<4;j++) \
        ldsm4(bf[2*j][0],bf[2*j][1],bf[2*j+1][0],bf[2*j+1][1], stg + lmB0 + j*2304 + (ks)*32); \
    _Pragma("unroll") \
    for (int nt=0;nt<8;nt++) \
        _Pragma("unroll") \
        for (int m2=0;m2<2;m2++) mma_f16(acc[m2][nt], af[m2], bf[nt]); \
} while(0)

    for (int kc=0; kc<NCH; kc++){
        const uint32_t stg = smemBase + (kc%NSTG)*STAGEB;
        if (kc+2 < NCH){
            const uint32_t dst = smemBase + ((kc+2)%NSTG)*STAGEB;
            const int ka = (kc+2)*64;
            #pragma unroll
            for (int j=0;j<4;j++) cp16(dst + offA[j], srcA[j] + ka);
            #pragma unroll
            for (int j=0;j<4;j++) cp16(dst + offB[j], srcB[j] + ka);
        }
        cp_commit();
        if (active){ DN_MMA(0); DN_MMA(1); DN_MMA(2); DN_MMA(3); }
        cp_wait1();
        __syncthreads();
    }
#undef DN_MMA

    if (active){
        #pragma unroll
        for (int m2=0;m2<2;m2++){
            const int rl0 = wm + m2*16 + fr;
            const int t0  = sTk[rl0];       const float w0 = sW[rl0];
            const int t1  = sTk[rl0+8];     const float w1 = sW[rl0+8];
            float* o0 = out + (size_t)t0*NH + n0;
            float* o1 = out + (size_t)t1*NH + n0;
            #pragma unroll
            for (int nt=0;nt<8;nt++){
                const int cg = wn + nt*8 + fc*2;
                const float b0 = sDb[cg], b1 = sDb[cg+1];
                if (rl0 < Mrows){
                    red_add(o0 + cg,     w0*(acc[m2][nt][0]+b0));
                    red_add(o0 + cg + 1, w0*(acc[m2][nt][1]+b1));
                }
                if (rl0+8 < Mrows){
                    red_add(o1 + cg,     w1*(acc[m2][nt][2]+b0));
                    red_add(o1 + cg + 1, w1*(acc[m2][nt][3]+b1));
                }
            }
        }
    }
}

// ---------------- launch: sliced dequant→gateup pipeline via event fork/join ----------------
extern "C" void kernel_launch(void* const* d_in, const int* in_sizes, int n_in,
                              void* d_out, int out_size)
{
    const float* x    = (const float*)d_in[0];
    const float* rw   = (const float*)d_in[1];
    const float* rb   = (const float*)d_in[2];
    const float* gblk = (const float*)d_in[3];
    const float* gscl = (const float*)d_in[4];
    const float* gbia = (const float*)d_in[5];
    const float* ublk = (const float*)d_in[6];
    const float* uscl = (const float*)d_in[7];
    const float* ubia = (const float*)d_in[8];
    const float* dblk = (const float*)d_in[9];
    const float* dscl = (const float*)d_in[10];
    const float* dbia = (const float*)d_in[11];
    float* out = (float*)d_out;

    static cudaStream_t s2 = nullptr;
    static cudaEvent_t eFork = nullptr, eDQ[NSLICE], eD = nullptr;
    if (!s2){
        cudaStreamCreateWithFlags(&s2, cudaStreamNonBlocking);
        cudaEventCreateWithFlags(&eFork, cudaEventDisableTiming);
        for (int c=0;c<NSLICE;c++) cudaEventCreateWithFlags(&eDQ[c], cudaEventDisableTiming);
        cudaEventCreateWithFlags(&eD, cudaEventDisableTiming);
        cudaFuncSetAttribute(gateup_full, cudaFuncAttributeMaxDynamicSharedMemorySize, DSMEM_BYTES);
        cudaFuncSetAttribute(down_kernel, cudaFuncAttributeMaxDynamicSharedMemorySize, DSMEM_BYTES);
    }

    const int SLICE_BLKS = (int)((size_t)NEXP*SLICE_I*NH/8/256);  // 8192
    const int DQBLKS = (int)(WELEM / 8 / 256);                    // 32768

    // fork s2 from default
    cudaEventRecord(eFork, 0);
    cudaStreamWaitEvent(s2, eFork, 0);

    // s2: dequant slices for gate+up, then down weights
    for (int c=0;c<NSLICE;c++){
        dequant_gu_slice<<<dim3(SLICE_BLKS, 2), 256, 0, s2>>>(gblk, gscl, ublk, uscl, c);
        cudaEventRecord(eDQ[c], s2);
    }
    dequant_d<<<DQBLKS, 256, 0, s2>>>(dblk, dscl);
    cudaEventRecord(eD, s2);

    // default: router (+zero out) -> lists -> gateup slices (each gated on its dequant)
    router_kernel<<<NT, 512>>>(x, rw, rb, out);
    build_lists_kernel<<<1, NT>>>();
    for (int c=0;c<NSLICE;c++){
        cudaStreamWaitEvent(0, eDQ[c], 0);
        gateup_full<<<dim3(8, NEXP*8), 256, DSMEM_BYTES>>>(gbia, ubia, c);
    }

    // join: down needs all gateup slices (stream-ordered) + dequant_d
    cudaStreamWaitEvent(0, eD, 0);
    down_kernel<<<dim3(NH/128, NEXP*8), 256, DSMEM_BYTES>>>(dbia, out);
}